// round 10
// baseline (speedup 1.0000x reference)
#include <cuda_runtime.h>
#include <cuda_bf16.h>
#include <cstddef>

// ---------------------------------------------------------------------------
// Problem constants
// ---------------------------------------------------------------------------
#define B_SZ      4096
#define IN_DIM    512
#define LATENT    512
#define NHEAD     8
#define DHEAD     64
#define KVB_N     (NHEAD * (2 * DHEAD + 1))   // 1032
#define LN_EPS    1e-5f

// ---------------------------------------------------------------------------
// Scratch (allocation-free: __device__ globals)
// ---------------------------------------------------------------------------
__device__ float g_h  [B_SZ * LATENT];
__device__ float g_h2 [B_SZ * LATENT];
__device__ float g_kvb[B_SZ * KVB_N];

// ---------------------------------------------------------------------------
// TF32 tensor-core GEMM v6 (v5 + MT template for grid-fill):
//   C[M,N] = A[M,K] @ B[K,N] + bias, A = concat(A0|A1) along K
// MT = m16-atoms per warp in M.  BM = 32*MT.  BN=128, BK=32.
//   MT=2: BM=64  -> G1/G2 grids 256 CTAs (full wave at occ 2)
//   MT=4: BM=128 -> G3 grid 288 CTAs (best measured shape)
// 256 threads = 8 warps (2 in M x 4 in N), warp tile (16*MT) x 32.
// 3-stage cp.async ring; one barrier per BK-iteration.
// A fragments via ldmatrix.x4; B via conflict-free scalar LDS.
// In-iteration fragment pipelining across the 4 k-steps.
// MODE 0: bias.  MODE 1: bias + kvb activations (tanh / sigmoid per head slot)
// ---------------------------------------------------------------------------
#define BN 128
#define BK 32
#define ASTRIDE 36    // 32 + 4 pad words
#define BSTRIDE 136   // 128 + 8 pad words
#define NSTAGE 3
#define BSZ (BK * BSTRIDE)   // 4352 words

__device__ __forceinline__ float kvb_act(float c, int n) {
    int r = n % 129;
    if (r >= 128) return 1.f / (1.f + __expf(-c));
    if (r >= 64)  return tanhf(c);
    return c;
}

template <int MODE, int MT>
__global__ __launch_bounds__(256, 2)
void tf32_gemm(const float* __restrict__ A0, const float* __restrict__ A1, int K0,
               const float* __restrict__ Bm, const float* __restrict__ bias,
               float* __restrict__ C, int N, int K)
{
    constexpr int BMt = 32 * MT;
    constexpr int ASZ = BMt * ASTRIDE;

    extern __shared__ float smem[];
    float* As = smem;
    float* Bs = smem + NSTAGE * ASZ;

    const int tid  = threadIdx.x;
    const int lane = tid & 31;
    const int wid  = tid >> 5;
    const int wm   = wid & 1;            // warp row (16*MT rows each)
    const int wn   = wid >> 1;           // warp col (32 cols each)
    const int m0   = blockIdx.y * BMt;
    const int n0   = blockIdx.x * BN;
    const int K1   = K - K0;
    const int g    = lane >> 2;          // 0..7
    const int t    = lane & 3;           // 0..3

    // LDSM per-lane address: lane L supplies row of matrix (L>>3)
    const int jj   = lane & 7;
    const int sel  = lane >> 3;
    const int arow = (sel & 1) * 8 + jj;
    const int acol = (sel >> 1) * 4;
    const unsigned As_base = (unsigned)__cvta_generic_to_shared(As);
    const unsigned a_lane  = ((wm * (16 * MT) + arow) * ASTRIDE + acol) * 4u;

    float acc[MT][4][4] = {};

    // ---------------- async tile loads ----------------
    auto load_tiles = [&](int it, int buf) {
        const int kb = it * BK;
        // A: BMt rows x 8 chunks of 16B -> MT units per thread
        #pragma unroll
        for (int u = 0; u < MT; ++u) {
            int idx = u * 256 + tid;
            int row = idx >> 3;
            int kc  = (idx & 7) * 4;
            int gk  = kb + kc;
            const float* src;
            if (gk < K0) src = A0 + (size_t)(m0 + row) * K0 + gk;
            else         src = A1 + (size_t)(m0 + row) * K1 + (gk - K0);
            unsigned dst = (unsigned)__cvta_generic_to_shared(
                               &As[buf * ASZ + row * ASTRIDE + kc]);
            asm volatile("cp.async.cg.shared.global [%0], [%1], 16;"
                         :: "r"(dst), "l"(src));
        }
        // B: 32 k-rows x 32 chunks of 16B -> 4 units per thread
        #pragma unroll
        for (int u = 0; u < 4; ++u) {
            int idx = u * 256 + tid;
            int k   = idx >> 5;
            int nc  = (idx & 31) * 4;
            unsigned dst = (unsigned)__cvta_generic_to_shared(
                               &Bs[buf * BSZ + k * BSTRIDE + nc]);
            if (MODE == 1) {
                int n = n0 + nc;
                int sz = (n < N) ? 16 : 0;                 // zfill OOB cols
                const float* src = Bm + (size_t)(kb + k) * N + (sz ? n : 0);
                asm volatile("cp.async.cg.shared.global [%0], [%1], 16, %2;"
                             :: "r"(dst), "l"(src), "r"(sz));
            } else {
                const float* src = Bm + (size_t)(kb + k) * N + (n0 + nc);
                asm volatile("cp.async.cg.shared.global [%0], [%1], 16;"
                             :: "r"(dst), "l"(src));
            }
        }
    };

    // ---------------- fragment loads ----------------
    auto ldA = [&](unsigned a[MT][4], int buf, int ks) {
        unsigned base = As_base + (unsigned)(buf * ASZ * 4) + a_lane
                      + (unsigned)(ks * 32);               // ks*8 words
        #pragma unroll
        for (int ma = 0; ma < MT; ++ma) {
            unsigned ad = base + (unsigned)(ma * 16 * ASTRIDE * 4);
            asm volatile("ldmatrix.sync.aligned.m8n8.x4.shared.b16 "
                         "{%0,%1,%2,%3}, [%4];"
                         : "=r"(a[ma][0]), "=r"(a[ma][1]),
                           "=r"(a[ma][2]), "=r"(a[ma][3])
                         : "r"(ad));
        }
    };
    auto ldB = [&](unsigned b[4][2], int buf, int ks) {
        const float* p = Bs + buf * BSZ + (ks * 8 + t) * BSTRIDE + wn * 32 + g;
        #pragma unroll
        for (int na = 0; na < 4; ++na) {
            b[na][0] = __float_as_uint(p[na * 8]);
            b[na][1] = __float_as_uint(p[na * 8 + 4 * BSTRIDE]);
        }
    };
    auto mmaMT = [&](unsigned a[MT][4], unsigned b[4][2]) {
        #pragma unroll
        for (int ma = 0; ma < MT; ++ma)
            #pragma unroll
            for (int na = 0; na < 4; ++na)
                asm volatile(
                    "mma.sync.aligned.m16n8k8.row.col.f32.tf32.tf32.f32 "
                    "{%0,%1,%2,%3}, {%4,%5,%6,%7}, {%8,%9}, {%0,%1,%2,%3};"
                    : "+f"(acc[ma][na][0]), "+f"(acc[ma][na][1]),
                      "+f"(acc[ma][na][2]), "+f"(acc[ma][na][3])
                    : "r"(a[ma][0]), "r"(a[ma][1]), "r"(a[ma][2]), "r"(a[ma][3]),
                      "r"(b[na][0]), "r"(b[na][1]));
    };

    // ---------------- main loop ----------------
    const int NT = K >> 5;
    load_tiles(0, 0); asm volatile("cp.async.commit_group;");
    load_tiles(1, 1); asm volatile("cp.async.commit_group;");

    unsigned aF[2][MT][4], bF[2][4][2];
    int buf = 0;
    for (int it = 0; it < NT; ++it) {
        asm volatile("cp.async.wait_group 1;");   // stage `it` arrived
        __syncthreads();                           // visible; prev compute done
        if (it + 2 < NT) {
            int b2 = buf + 2; if (b2 >= NSTAGE) b2 -= NSTAGE;
            load_tiles(it + 2, b2);                // overwrites stage it-1 buf
        }
        asm volatile("cp.async.commit_group;");    // may be empty

        // 4 k-steps with fragment pipelining
        ldA(aF[0], buf, 0); ldB(bF[0], buf, 0);
        #pragma unroll
        for (int s = 0; s < 4; ++s) {
            if (s < 3) { ldA(aF[(s + 1) & 1], buf, s + 1);
                         ldB(bF[(s + 1) & 1], buf, s + 1); }
            mmaMT(aF[s & 1], bF[s & 1]);
        }
        ++buf; if (buf == NSTAGE) buf = 0;
    }

    // ---------------- epilogue ----------------
    #pragma unroll
    for (int ma = 0; ma < MT; ++ma) {
        int row = m0 + wm * (16 * MT) + ma * 16 + g;
        #pragma unroll
        for (int na = 0; na < 4; ++na) {
            int nb = n0 + wn * 32 + na * 8;
            if (MODE == 0 || nb < N) {           // N multiple of 8
                int n = nb + t * 2;
                float bx = bias[n], by = bias[n + 1];
                float c0 = acc[ma][na][0] + bx;
                float c1 = acc[ma][na][1] + by;
                float c2 = acc[ma][na][2] + bx;
                float c3 = acc[ma][na][3] + by;
                if (MODE == 1) {
                    c0 = kvb_act(c0, n);   c1 = kvb_act(c1, n + 1);
                    c2 = kvb_act(c2, n);   c3 = kvb_act(c3, n + 1);
                }
                *(float2*)&C[(size_t)row * N + n]       = make_float2(c0, c1);
                *(float2*)&C[(size_t)(row + 8) * N + n] = make_float2(c2, c3);
            }
        }
    }
}

// ---------------------------------------------------------------------------
// In-place LayerNorm over rows of 512.  4096 blocks x 128 threads.
// ---------------------------------------------------------------------------
__global__ __launch_bounds__(128)
void ln_kernel(float* __restrict__ h, const float* __restrict__ g,
               const float* __restrict__ b)
{
    const int row = blockIdx.x;
    float* hp = h + (size_t)row * LATENT;
    const int tid = threadIdx.x;

    float4 v = ((const float4*)hp)[tid];
    float s  = v.x + v.y + v.z + v.w;
    float sq = v.x * v.x + v.y * v.y + v.z * v.z + v.w * v.w;

    __shared__ float rs[4], rq[4];
    #pragma unroll
    for (int o = 16; o; o >>= 1) {
        s  += __shfl_xor_sync(0xffffffffu, s,  o);
        sq += __shfl_xor_sync(0xffffffffu, sq, o);
    }
    if ((tid & 31) == 0) { rs[tid >> 5] = s; rq[tid >> 5] = sq; }
    __syncthreads();
    s  = rs[0] + rs[1] + rs[2] + rs[3];
    sq = rq[0] + rq[1] + rq[2] + rq[3];

    const float mu  = s * (1.f / LATENT);
    const float var = sq * (1.f / LATENT) - mu * mu;
    const float inv = rsqrtf(var + LN_EPS);

    float4 gg = ((const float4*)g)[tid];
    float4 bb = ((const float4*)b)[tid];
    v.x = (v.x - mu) * inv * gg.x + bb.x;
    v.y = (v.y - mu) * inv * gg.y + bb.y;
    v.z = (v.z - mu) * inv * gg.z + bb.z;
    v.w = (v.w - mu) * inv * gg.w + bb.w;
    ((float4*)hp)[tid] = v;
}

// ---------------------------------------------------------------------------
// Fused Oja update v2 (vectorized).  One CTA per (b,h).
// 256 threads: c4 = tid&15 (4-col group), r4 = tid>>4 (4-row slab).
// Each thread holds a 4x4 register tile of W: 4 LDG.128 + 4 STG.128.
//   ks_remove[e] = sum_d W[d,e]*vs[d];  ks_ = softmax(ks-ks_remove)*lr
//   out[d,e] = vs[d]*ks_[e] + W[d,e]
// ---------------------------------------------------------------------------
__global__ __launch_bounds__(256)
void oja_kernel(const float* __restrict__ kvb, const float* __restrict__ W,
                float* __restrict__ out)
{
    const int bh = blockIdx.x;
    const int b  = bh >> 3;
    const int h  = bh & 7;

    const float*  kb  = kvb + (size_t)b * KVB_N + h * 129;
    const float4* Wp4 = (const float4*)(W   + (size_t)bh * (DHEAD * DHEAD));
    float4*       Op4 = (float4*)      (out + (size_t)bh * (DHEAD * DHEAD));

    __shared__ float ks_s[64], vs_s[64], ksf[64];
    __shared__ float red[16][64];
    __shared__ float wred[8];
    __shared__ float lr_s;

    const int tid = threadIdx.x;
    if (tid < 64)       { ks_s[tid] = kb[tid]; vs_s[tid] = kb[64 + tid]; }
    else if (tid == 64) { lr_s = kb[128]; }
    __syncthreads();

    const int c4 = tid & 15;     // column group (cols 4*c4 .. 4*c4+3)
    const int r4 = tid >> 4;     // row slab    (rows 4*r4 .. 4*r4+3)

    float4 w4[4];
    float4 ps = make_float4(0.f, 0.f, 0.f, 0.f);
    #pragma unroll
    for (int i = 0; i < 4; ++i) {
        int d = r4 * 4 + i;
        w4[i] = Wp4[d * 16 + c4];            // 2x256B per warp, coalesced
        float v = vs_s[d];
        ps.x = fmaf(w4[i].x, v, ps.x);
        ps.y = fmaf(w4[i].y, v, ps.y);
        ps.z = fmaf(w4[i].z, v, ps.z);
        ps.w = fmaf(w4[i].w, v, ps.w);
    }
    *(float4*)&red[r4][c4 * 4] = ps;
    __syncthreads();

    // --- softmax over e (uniform control flow; tid>=64 carry neutral values)
    float v = -1e30f;
    if (tid < 64) {
        float rem = 0.f;
        #pragma unroll
        for (int s = 0; s < 16; ++s) rem += red[s][tid];
        v = ks_s[tid] - rem;
    }

    float m = v;
    #pragma unroll
    for (int o = 16; o; o >>= 1) m = fmaxf(m, __shfl_xor_sync(0xffffffffu, m, o));
    if ((tid & 31) == 0) wred[tid >> 5] = m;
    __syncthreads();
    m = wred[0];
    #pragma unroll
    for (int i = 1; i < 8; ++i) m = fmaxf(m, wred[i]);
    __syncthreads();                                  // before reusing wred

    float ex = (tid < 64) ? __expf(v - m) : 0.f;
    float sm = ex;
    #pragma unroll
    for (int o = 16; o; o >>= 1) sm += __shfl_xor_sync(0xffffffffu, sm, o);
    if ((tid & 31) == 0) wred[tid >> 5] = sm;
    __syncthreads();
    sm = wred[0] + wred[1] + wred[2] + wred[3] + wred[4] + wred[5] + wred[6] + wred[7];

    if (tid < 64) ksf[tid] = ex * lr_s / sm;
    __syncthreads();

    const float4 kf = *(const float4*)&ksf[c4 * 4];
    #pragma unroll
    for (int i = 0; i < 4; ++i) {
        int d = r4 * 4 + i;
        float v2 = vs_s[d];
        float4 o;
        o.x = fmaf(v2, kf.x, w4[i].x);
        o.y = fmaf(v2, kf.y, w4[i].y);
        o.z = fmaf(v2, kf.z, w4[i].z);
        o.w = fmaf(v2, kf.w, w4[i].w);
        Op4[d * 16 + c4] = o;
    }
}

// ---------------------------------------------------------------------------
// Launch
// ---------------------------------------------------------------------------
extern "C" void kernel_launch(void* const* d_in, const int* in_sizes, int n_in,
                              void* d_out, int out_size)
{
    const float* x     = (const float*)d_in[0];
    const float* z     = (const float*)d_in[1];
    const float* W     = (const float*)d_in[2];
    const float* ip_w  = (const float*)d_in[3];
    const float* ip_b  = (const float*)d_in[4];
    const float* ln_g  = (const float*)d_in[5];
    const float* ln_b  = (const float*)d_in[6];
    const float* mg_w  = (const float*)d_in[7];
    const float* mg_b  = (const float*)d_in[8];
    const float* kvb_w = (const float*)d_in[9];
    const float* kvb_b = (const float*)d_in[10];
    float* out = (float*)d_out;

    void *ph, *ph2, *pkvb;
    cudaGetSymbolAddress(&ph,   g_h);
    cudaGetSymbolAddress(&ph2,  g_h2);
    cudaGetSymbolAddress(&pkvb, g_kvb);
    float* h   = (float*)ph;
    float* h2  = (float*)ph2;
    float* kvb = (float*)pkvb;

    constexpr int SM_MT2 = NSTAGE * (64  * ASTRIDE + BSZ) * 4;   //  79872 B
    constexpr int SM_MT4 = NSTAGE * (128 * ASTRIDE + BSZ) * 4;   // 107520 B

    cudaFuncSetAttribute(tf32_gemm<0, 2>,
                         cudaFuncAttributeMaxDynamicSharedMemorySize, SM_MT2);
    cudaFuncSetAttribute(tf32_gemm<1, 4>,
                         cudaFuncAttributeMaxDynamicSharedMemorySize, SM_MT4);

    // 1) h = x @ ip_w + ip_b               (M=4096, N=512, K=512)   256 CTAs
    tf32_gemm<0, 2><<<dim3(LATENT / BN, B_SZ / 64), 256, SM_MT2>>>(
        x, nullptr, IN_DIM, ip_w, ip_b, h, LATENT, IN_DIM);

    // 2) LayerNorm in place
    ln_kernel<<<B_SZ, 128>>>(h, ln_g, ln_b);

    // 3) h2 = concat(h, z) @ mg_w + mg_b   (K=1024, split at 512)   256 CTAs
    tf32_gemm<0, 2><<<dim3(LATENT / BN, B_SZ / 64), 256, SM_MT2>>>(
        h, z, LATENT, mg_w, mg_b, h2, LATENT, 2 * LATENT);

    // 4) kvb = act(h2 @ kvb_w + kvb_b)     (N=1032)                 288 CTAs
    tf32_gemm<1, 4><<<dim3((KVB_N + BN - 1) / BN, B_SZ / 128), 256, SM_MT4>>>(
        h2, nullptr, LATENT, kvb_w, kvb_b, kvb, KVB_N, LATENT);

    // 5) fused Oja update                  (32768 CTAs, DRAM-bound)
    oja_kernel<<<B_SZ * NHEAD, 256>>>(kvb, W, out);
}

// round 15
// speedup vs baseline: 1.0325x; 1.0325x over previous
#include <cuda_runtime.h>
#include <cuda_bf16.h>
#include <cstddef>

// ---------------------------------------------------------------------------
// Problem constants
// ---------------------------------------------------------------------------
#define B_SZ      4096
#define IN_DIM    512
#define LATENT    512
#define NHEAD     8
#define DHEAD     64
#define KVB_N     (NHEAD * (2 * DHEAD + 1))   // 1032
#define LN_EPS    1e-5f

// ---------------------------------------------------------------------------
// Scratch (allocation-free: __device__ globals)
// ---------------------------------------------------------------------------
__device__ float g_h  [B_SZ * LATENT];
__device__ float g_h2 [B_SZ * LATENT];
__device__ float g_kvb[B_SZ * KVB_N];

// ---------------------------------------------------------------------------
// TF32 tensor-core GEMM (R9-best configuration):
//   C[M,N] = A[M,K] @ B[K,N] + bias, A = concat(A0|A1) along K
// BM=128 BN=128 BK=32, 256 threads = 8 warps (2 in M x 4 in N),
// warp tile 64x32 = 4x4 m16n8k8 atoms, 2 CTAs/SM.
// 3-stage cp.async ring; one barrier per BK-iteration.
// A fragments via ldmatrix.x4; B via conflict-free scalar LDS
// (banks 8t+g all distinct).  In-iteration fragment pipelining (4 k-steps).
// MODE 0: bias.  MODE 1: bias + kvb activations (tanh / sigmoid per head slot)
// ---------------------------------------------------------------------------
#define BN 128
#define BK 32
#define ASTRIDE 36    // 32 + 4 pad words
#define BSTRIDE 136   // 128 + 8 pad words
#define NSTAGE 3
#define BSZ (BK * BSTRIDE)   // 4352 words

__device__ __forceinline__ float kvb_act(float c, int n) {
    int r = n % 129;
    if (r >= 128) return 1.f / (1.f + __expf(-c));
    if (r >= 64)  return tanhf(c);
    return c;
}

template <int MODE, int MT>
__global__ __launch_bounds__(256, 2)
void tf32_gemm(const float* __restrict__ A0, const float* __restrict__ A1, int K0,
               const float* __restrict__ Bm, const float* __restrict__ bias,
               float* __restrict__ C, int N, int K)
{
    constexpr int BMt = 32 * MT;
    constexpr int ASZ = BMt * ASTRIDE;

    extern __shared__ float smem[];
    float* As = smem;
    float* Bs = smem + NSTAGE * ASZ;

    const int tid  = threadIdx.x;
    const int lane = tid & 31;
    const int wid  = tid >> 5;
    const int wm   = wid & 1;            // warp row (16*MT rows each)
    const int wn   = wid >> 1;           // warp col (32 cols each)
    const int m0   = blockIdx.y * BMt;
    const int n0   = blockIdx.x * BN;
    const int K1   = K - K0;
    const int g    = lane >> 2;          // 0..7
    const int t    = lane & 3;           // 0..3

    // LDSM per-lane address: lane L supplies row of matrix (L>>3)
    const int jj   = lane & 7;
    const int sel  = lane >> 3;
    const int arow = (sel & 1) * 8 + jj;
    const int acol = (sel >> 1) * 4;
    const unsigned As_base = (unsigned)__cvta_generic_to_shared(As);
    const unsigned a_lane  = ((wm * (16 * MT) + arow) * ASTRIDE + acol) * 4u;

    float acc[MT][4][4] = {};

    // ---------------- async tile loads ----------------
    auto load_tiles = [&](int it, int buf) {
        const int kb = it * BK;
        #pragma unroll
        for (int u = 0; u < MT; ++u) {
            int idx = u * 256 + tid;
            int row = idx >> 3;
            int kc  = (idx & 7) * 4;
            int gk  = kb + kc;
            const float* src;
            if (gk < K0) src = A0 + (size_t)(m0 + row) * K0 + gk;
            else         src = A1 + (size_t)(m0 + row) * K1 + (gk - K0);
            unsigned dst = (unsigned)__cvta_generic_to_shared(
                               &As[buf * ASZ + row * ASTRIDE + kc]);
            asm volatile("cp.async.cg.shared.global [%0], [%1], 16;"
                         :: "r"(dst), "l"(src));
        }
        #pragma unroll
        for (int u = 0; u < 4; ++u) {
            int idx = u * 256 + tid;
            int k   = idx >> 5;
            int nc  = (idx & 31) * 4;
            unsigned dst = (unsigned)__cvta_generic_to_shared(
                               &Bs[buf * BSZ + k * BSTRIDE + nc]);
            if (MODE == 1) {
                int n = n0 + nc;
                int sz = (n < N) ? 16 : 0;                 // zfill OOB cols
                const float* src = Bm + (size_t)(kb + k) * N + (sz ? n : 0);
                asm volatile("cp.async.cg.shared.global [%0], [%1], 16, %2;"
                             :: "r"(dst), "l"(src), "r"(sz));
            } else {
                const float* src = Bm + (size_t)(kb + k) * N + (n0 + nc);
                asm volatile("cp.async.cg.shared.global [%0], [%1], 16;"
                             :: "r"(dst), "l"(src));
            }
        }
    };

    // ---------------- fragment loads ----------------
    auto ldA = [&](unsigned a[MT][4], int buf, int ks) {
        unsigned base = As_base + (unsigned)(buf * ASZ * 4) + a_lane
                      + (unsigned)(ks * 32);               // ks*8 words
        #pragma unroll
        for (int ma = 0; ma < MT; ++ma) {
            unsigned ad = base + (unsigned)(ma * 16 * ASTRIDE * 4);
            asm volatile("ldmatrix.sync.aligned.m8n8.x4.shared.b16 "
                         "{%0,%1,%2,%3}, [%4];"
                         : "=r"(a[ma][0]), "=r"(a[ma][1]),
                           "=r"(a[ma][2]), "=r"(a[ma][3])
                         : "r"(ad));
        }
    };
    auto ldB = [&](unsigned b[4][2], int buf, int ks) {
        const float* p = Bs + buf * BSZ + (ks * 8 + t) * BSTRIDE + wn * 32 + g;
        #pragma unroll
        for (int na = 0; na < 4; ++na) {
            b[na][0] = __float_as_uint(p[na * 8]);
            b[na][1] = __float_as_uint(p[na * 8 + 4 * BSTRIDE]);
        }
    };
    auto mmaMT = [&](unsigned a[MT][4], unsigned b[4][2]) {
        #pragma unroll
        for (int ma = 0; ma < MT; ++ma)
            #pragma unroll
            for (int na = 0; na < 4; ++na)
                asm volatile(
                    "mma.sync.aligned.m16n8k8.row.col.f32.tf32.tf32.f32 "
                    "{%0,%1,%2,%3}, {%4,%5,%6,%7}, {%8,%9}, {%0,%1,%2,%3};"
                    : "+f"(acc[ma][na][0]), "+f"(acc[ma][na][1]),
                      "+f"(acc[ma][na][2]), "+f"(acc[ma][na][3])
                    : "r"(a[ma][0]), "r"(a[ma][1]), "r"(a[ma][2]), "r"(a[ma][3]),
                      "r"(b[na][0]), "r"(b[na][1]));
    };

    // ---------------- main loop ----------------
    const int NT = K >> 5;
    load_tiles(0, 0); asm volatile("cp.async.commit_group;");
    load_tiles(1, 1); asm volatile("cp.async.commit_group;");

    unsigned aF[2][MT][4], bF[2][4][2];
    int buf = 0;
    for (int it = 0; it < NT; ++it) {
        asm volatile("cp.async.wait_group 1;");   // stage `it` arrived
        __syncthreads();                           // visible; prev compute done
        if (it + 2 < NT) {
            int b2 = buf + 2; if (b2 >= NSTAGE) b2 -= NSTAGE;
            load_tiles(it + 2, b2);                // overwrites stage it-1 buf
        }
        asm volatile("cp.async.commit_group;");    // may be empty

        // 4 k-steps with fragment pipelining
        ldA(aF[0], buf, 0); ldB(bF[0], buf, 0);
        #pragma unroll
        for (int s = 0; s < 4; ++s) {
            if (s < 3) { ldA(aF[(s + 1) & 1], buf, s + 1);
                         ldB(bF[(s + 1) & 1], buf, s + 1); }
            mmaMT(aF[s & 1], bF[s & 1]);
        }
        ++buf; if (buf == NSTAGE) buf = 0;
    }

    // ---------------- epilogue ----------------
    #pragma unroll
    for (int ma = 0; ma < MT; ++ma) {
        int row = m0 + wm * (16 * MT) + ma * 16 + g;
        #pragma unroll
        for (int na = 0; na < 4; ++na) {
            int nb = n0 + wn * 32 + na * 8;
            if (MODE == 0 || nb < N) {           // N multiple of 8
                int n = nb + t * 2;
                float bx = bias[n], by = bias[n + 1];
                float c0 = acc[ma][na][0] + bx;
                float c1 = acc[ma][na][1] + by;
                float c2 = acc[ma][na][2] + bx;
                float c3 = acc[ma][na][3] + by;
                if (MODE == 1) {
                    c0 = kvb_act(c0, n);   c1 = kvb_act(c1, n + 1);
                    c2 = kvb_act(c2, n);   c3 = kvb_act(c3, n + 1);
                }
                *(float2*)&C[(size_t)row * N + n]       = make_float2(c0, c1);
                *(float2*)&C[(size_t)(row + 8) * N + n] = make_float2(c2, c3);
            }
        }
    }
}

// ---------------------------------------------------------------------------
// In-place LayerNorm over rows of 512.  4096 blocks x 128 threads.
// ---------------------------------------------------------------------------
__global__ __launch_bounds__(128)
void ln_kernel(float* __restrict__ h, const float* __restrict__ g,
               const float* __restrict__ b)
{
    const int row = blockIdx.x;
    float* hp = h + (size_t)row * LATENT;
    const int tid = threadIdx.x;

    float4 v = ((const float4*)hp)[tid];
    float s  = v.x + v.y + v.z + v.w;
    float sq = v.x * v.x + v.y * v.y + v.z * v.z + v.w * v.w;

    __shared__ float rs[4], rq[4];
    #pragma unroll
    for (int o = 16; o; o >>= 1) {
        s  += __shfl_xor_sync(0xffffffffu, s,  o);
        sq += __shfl_xor_sync(0xffffffffu, sq, o);
    }
    if ((tid & 31) == 0) { rs[tid >> 5] = s; rq[tid >> 5] = sq; }
    __syncthreads();
    s  = rs[0] + rs[1] + rs[2] + rs[3];
    sq = rq[0] + rq[1] + rq[2] + rq[3];

    const float mu  = s * (1.f / LATENT);
    const float var = sq * (1.f / LATENT) - mu * mu;
    const float inv = rsqrtf(var + LN_EPS);

    float4 gg = ((const float4*)g)[tid];
    float4 bb = ((const float4*)b)[tid];
    v.x = (v.x - mu) * inv * gg.x + bb.x;
    v.y = (v.y - mu) * inv * gg.y + bb.y;
    v.z = (v.z - mu) * inv * gg.z + bb.z;
    v.w = (v.w - mu) * inv * gg.w + bb.w;
    ((float4*)hp)[tid] = v;
}

// ---------------------------------------------------------------------------
// Fused Oja update (R9 layout + streaming cache hints).
// One CTA per (b,h): 64x64 W tile in registers.
//   ks_remove[e] = sum_d W[d,e]*vs[d];  ks_ = softmax(ks-ks_remove)*lr
//   out[d,e] = vs[d]*ks_[e] + W[d,e]
// W is 512MB read-once -> __ldcs;  out is 512MB write-once -> __stcs.
// ---------------------------------------------------------------------------
__global__ __launch_bounds__(256)
void oja_kernel(const float* __restrict__ kvb, const float* __restrict__ W,
                float* __restrict__ out)
{
    const int bh = blockIdx.x;
    const int b  = bh >> 3;
    const int h  = bh & 7;

    const float* kb = kvb + (size_t)b * KVB_N + h * 129;
    const float* Wp = W   + (size_t)bh * (DHEAD * DHEAD);
    float*       Op = out + (size_t)bh * (DHEAD * DHEAD);

    __shared__ float ks_s[64], vs_s[64], ksf[64];
    __shared__ float red4[4 * 64];
    __shared__ float wred[8];
    __shared__ float lr_s;

    const int tid = threadIdx.x;
    if (tid < 64)       { ks_s[tid] = kb[tid]; vs_s[tid] = kb[64 + tid]; }
    else if (tid == 64) { lr_s = kb[128]; }
    __syncthreads();

    const int e = tid & 63;
    const int q = tid >> 6;

    float w[16];
    float partial = 0.f;
    #pragma unroll
    for (int i = 0; i < 16; ++i) {
        int d = q * 16 + i;
        w[i] = __ldcs(Wp + d * 64 + e);              // streaming read
        partial = fmaf(w[i], vs_s[d], partial);
    }
    red4[q * 64 + e] = partial;
    __syncthreads();

    float v = -1e30f;
    if (tid < 64)
        v = ks_s[e] - (red4[e] + red4[64 + e] + red4[128 + e] + red4[192 + e]);

    float m = v;
    #pragma unroll
    for (int o = 16; o; o >>= 1) m = fmaxf(m, __shfl_xor_sync(0xffffffffu, m, o));
    if ((tid & 31) == 0) wred[tid >> 5] = m;
    __syncthreads();
    m = wred[0];
    #pragma unroll
    for (int i = 1; i < 8; ++i) m = fmaxf(m, wred[i]);
    __syncthreads();

    float ex = (tid < 64) ? __expf(v - m) : 0.f;
    float sm = ex;
    #pragma unroll
    for (int o = 16; o; o >>= 1) sm += __shfl_xor_sync(0xffffffffu, sm, o);
    if ((tid & 31) == 0) wred[tid >> 5] = sm;
    __syncthreads();
    sm = wred[0] + wred[1] + wred[2] + wred[3] + wred[4] + wred[5] + wred[6] + wred[7];

    if (tid < 64) ksf[e] = ex * lr_s / sm;
    __syncthreads();

    const float ke = ksf[e];
    #pragma unroll
    for (int i = 0; i < 16; ++i) {
        int d = q * 16 + i;
        __stcs(Op + d * 64 + e, fmaf(vs_s[d], ke, w[i]));   // streaming write
    }
}

// ---------------------------------------------------------------------------
// Launch (R9 grids: MT=4 / BM=128 everywhere)
// ---------------------------------------------------------------------------
extern "C" void kernel_launch(void* const* d_in, const int* in_sizes, int n_in,
                              void* d_out, int out_size)
{
    const float* x     = (const float*)d_in[0];
    const float* z     = (const float*)d_in[1];
    const float* W     = (const float*)d_in[2];
    const float* ip_w  = (const float*)d_in[3];
    const float* ip_b  = (const float*)d_in[4];
    const float* ln_g  = (const float*)d_in[5];
    const float* ln_b  = (const float*)d_in[6];
    const float* mg_w  = (const float*)d_in[7];
    const float* mg_b  = (const float*)d_in[8];
    const float* kvb_w = (const float*)d_in[9];
    const float* kvb_b = (const float*)d_in[10];
    float* out = (float*)d_out;

    void *ph, *ph2, *pkvb;
    cudaGetSymbolAddress(&ph,   g_h);
    cudaGetSymbolAddress(&ph2,  g_h2);
    cudaGetSymbolAddress(&pkvb, g_kvb);
    float* h   = (float*)ph;
    float* h2  = (float*)ph2;
    float* kvb = (float*)pkvb;

    constexpr int SM_MT4 = NSTAGE * (128 * ASTRIDE + BSZ) * 4;   // 107520 B

    cudaFuncSetAttribute(tf32_gemm<0, 4>,
                         cudaFuncAttributeMaxDynamicSharedMemorySize, SM_MT4);
    cudaFuncSetAttribute(tf32_gemm<1, 4>,
                         cudaFuncAttributeMaxDynamicSharedMemorySize, SM_MT4);

    // 1) h = x @ ip_w + ip_b               (M=4096, N=512, K=512)   128 CTAs
    tf32_gemm<0, 4><<<dim3(LATENT / BN, B_SZ / 128), 256, SM_MT4>>>(
        x, nullptr, IN_DIM, ip_w, ip_b, h, LATENT, IN_DIM);

    // 2) LayerNorm in place
    ln_kernel<<<B_SZ, 128>>>(h, ln_g, ln_b);

    // 3) h2 = concat(h, z) @ mg_w + mg_b   (K=1024, split at 512)   128 CTAs
    tf32_gemm<0, 4><<<dim3(LATENT / BN, B_SZ / 128), 256, SM_MT4>>>(
        h, z, LATENT, mg_w, mg_b, h2, LATENT, 2 * LATENT);

    // 4) kvb = act(h2 @ kvb_w + kvb_b)     (N=1032)                 288 CTAs
    tf32_gemm<1, 4><<<dim3((KVB_N + BN - 1) / BN, B_SZ / 128), 256, SM_MT4>>>(
        h2, nullptr, LATENT, kvb_w, kvb_b, kvb, KVB_N, LATENT);

    // 5) fused Oja update                  (32768 CTAs, DRAM-bound)
    oja_kernel<<<B_SZ * NHEAD, 256>>>(kvb, W, out);
}

// round 16
// speedup vs baseline: 1.0390x; 1.0063x over previous
#include <cuda_runtime.h>
#include <cuda_bf16.h>
#include <cstddef>

// ---------------------------------------------------------------------------
// Problem constants
// ---------------------------------------------------------------------------
#define B_SZ      4096
#define IN_DIM    512
#define LATENT    512
#define NHEAD     8
#define DHEAD     64
#define KVB_N     (NHEAD * (2 * DHEAD + 1))   // 1032
#define LN_EPS    1e-5f

// ---------------------------------------------------------------------------
// Scratch (allocation-free: __device__ globals)
// ---------------------------------------------------------------------------
__device__ float g_h  [B_SZ * LATENT];
__device__ float g_h2 [B_SZ * LATENT];
__device__ float g_kvb[B_SZ * KVB_N];

// ---------------------------------------------------------------------------
// TF32 tensor-core GEMM (R9-best configuration, frozen):
//   C[M,N] = A[M,K] @ B[K,N] + bias, A = concat(A0|A1) along K
// BM=128 BN=128 BK=32, 256 threads = 8 warps (2 in M x 4 in N),
// warp tile 64x32 = 4x4 m16n8k8 atoms, 2 CTAs/SM.
// 3-stage cp.async ring; one barrier per BK-iteration.
// A fragments via ldmatrix.x4; B via conflict-free scalar LDS.
// MODE 0: bias.  MODE 1: bias + kvb activations (tanh / sigmoid per head slot)
// ---------------------------------------------------------------------------
#define BN 128
#define BK 32
#define ASTRIDE 36    // 32 + 4 pad words
#define BSTRIDE 136   // 128 + 8 pad words
#define NSTAGE 3
#define BSZ (BK * BSTRIDE)   // 4352 words

__device__ __forceinline__ float kvb_act(float c, int n) {
    int r = n % 129;
    if (r >= 128) return 1.f / (1.f + __expf(-c));
    if (r >= 64)  return tanhf(c);
    return c;
}

template <int MODE, int MT>
__global__ __launch_bounds__(256, 2)
void tf32_gemm(const float* __restrict__ A0, const float* __restrict__ A1, int K0,
               const float* __restrict__ Bm, const float* __restrict__ bias,
               float* __restrict__ C, int N, int K)
{
    constexpr int BMt = 32 * MT;
    constexpr int ASZ = BMt * ASTRIDE;

    extern __shared__ float smem[];
    float* As = smem;
    float* Bs = smem + NSTAGE * ASZ;

    const int tid  = threadIdx.x;
    const int lane = tid & 31;
    const int wid  = tid >> 5;
    const int wm   = wid & 1;
    const int wn   = wid >> 1;
    const int m0   = blockIdx.y * BMt;
    const int n0   = blockIdx.x * BN;
    const int K1   = K - K0;
    const int g    = lane >> 2;
    const int t    = lane & 3;

    const int jj   = lane & 7;
    const int sel  = lane >> 3;
    const int arow = (sel & 1) * 8 + jj;
    const int acol = (sel >> 1) * 4;
    const unsigned As_base = (unsigned)__cvta_generic_to_shared(As);
    const unsigned a_lane  = ((wm * (16 * MT) + arow) * ASTRIDE + acol) * 4u;

    float acc[MT][4][4] = {};

    auto load_tiles = [&](int it, int buf) {
        const int kb = it * BK;
        #pragma unroll
        for (int u = 0; u < MT; ++u) {
            int idx = u * 256 + tid;
            int row = idx >> 3;
            int kc  = (idx & 7) * 4;
            int gk  = kb + kc;
            const float* src;
            if (gk < K0) src = A0 + (size_t)(m0 + row) * K0 + gk;
            else         src = A1 + (size_t)(m0 + row) * K1 + (gk - K0);
            unsigned dst = (unsigned)__cvta_generic_to_shared(
                               &As[buf * ASZ + row * ASTRIDE + kc]);
            asm volatile("cp.async.cg.shared.global [%0], [%1], 16;"
                         :: "r"(dst), "l"(src));
        }
        #pragma unroll
        for (int u = 0; u < 4; ++u) {
            int idx = u * 256 + tid;
            int k   = idx >> 5;
            int nc  = (idx & 31) * 4;
            unsigned dst = (unsigned)__cvta_generic_to_shared(
                               &Bs[buf * BSZ + k * BSTRIDE + nc]);
            if (MODE == 1) {
                int n = n0 + nc;
                int sz = (n < N) ? 16 : 0;                 // zfill OOB cols
                const float* src = Bm + (size_t)(kb + k) * N + (sz ? n : 0);
                asm volatile("cp.async.cg.shared.global [%0], [%1], 16, %2;"
                             :: "r"(dst), "l"(src), "r"(sz));
            } else {
                const float* src = Bm + (size_t)(kb + k) * N + (n0 + nc);
                asm volatile("cp.async.cg.shared.global [%0], [%1], 16;"
                             :: "r"(dst), "l"(src));
            }
        }
    };

    auto ldA = [&](unsigned a[MT][4], int buf, int ks) {
        unsigned base = As_base + (unsigned)(buf * ASZ * 4) + a_lane
                      + (unsigned)(ks * 32);
        #pragma unroll
        for (int ma = 0; ma < MT; ++ma) {
            unsigned ad = base + (unsigned)(ma * 16 * ASTRIDE * 4);
            asm volatile("ldmatrix.sync.aligned.m8n8.x4.shared.b16 "
                         "{%0,%1,%2,%3}, [%4];"
                         : "=r"(a[ma][0]), "=r"(a[ma][1]),
                           "=r"(a[ma][2]), "=r"(a[ma][3])
                         : "r"(ad));
        }
    };
    auto ldB = [&](unsigned b[4][2], int buf, int ks) {
        const float* p = Bs + buf * BSZ + (ks * 8 + t) * BSTRIDE + wn * 32 + g;
        #pragma unroll
        for (int na = 0; na < 4; ++na) {
            b[na][0] = __float_as_uint(p[na * 8]);
            b[na][1] = __float_as_uint(p[na * 8 + 4 * BSTRIDE]);
        }
    };
    auto mmaMT = [&](unsigned a[MT][4], unsigned b[4][2]) {
        #pragma unroll
        for (int ma = 0; ma < MT; ++ma)
            #pragma unroll
            for (int na = 0; na < 4; ++na)
                asm volatile(
                    "mma.sync.aligned.m16n8k8.row.col.f32.tf32.tf32.f32 "
                    "{%0,%1,%2,%3}, {%4,%5,%6,%7}, {%8,%9}, {%0,%1,%2,%3};"
                    : "+f"(acc[ma][na][0]), "+f"(acc[ma][na][1]),
                      "+f"(acc[ma][na][2]), "+f"(acc[ma][na][3])
                    : "r"(a[ma][0]), "r"(a[ma][1]), "r"(a[ma][2]), "r"(a[ma][3]),
                      "r"(b[na][0]), "r"(b[na][1]));
    };

    const int NT = K >> 5;
    load_tiles(0, 0); asm volatile("cp.async.commit_group;");
    load_tiles(1, 1); asm volatile("cp.async.commit_group;");

    unsigned aF[2][MT][4], bF[2][4][2];
    int buf = 0;
    for (int it = 0; it < NT; ++it) {
        asm volatile("cp.async.wait_group 1;");
        __syncthreads();
        if (it + 2 < NT) {
            int b2 = buf + 2; if (b2 >= NSTAGE) b2 -= NSTAGE;
            load_tiles(it + 2, b2);
        }
        asm volatile("cp.async.commit_group;");

        ldA(aF[0], buf, 0); ldB(bF[0], buf, 0);
        #pragma unroll
        for (int s = 0; s < 4; ++s) {
            if (s < 3) { ldA(aF[(s + 1) & 1], buf, s + 1);
                         ldB(bF[(s + 1) & 1], buf, s + 1); }
            mmaMT(aF[s & 1], bF[s & 1]);
        }
        ++buf; if (buf == NSTAGE) buf = 0;
    }

    #pragma unroll
    for (int ma = 0; ma < MT; ++ma) {
        int row = m0 + wm * (16 * MT) + ma * 16 + g;
        #pragma unroll
        for (int na = 0; na < 4; ++na) {
            int nb = n0 + wn * 32 + na * 8;
            if (MODE == 0 || nb < N) {
                int n = nb + t * 2;
                float bx = bias[n], by = bias[n + 1];
                float c0 = acc[ma][na][0] + bx;
                float c1 = acc[ma][na][1] + by;
                float c2 = acc[ma][na][2] + bx;
                float c3 = acc[ma][na][3] + by;
                if (MODE == 1) {
                    c0 = kvb_act(c0, n);   c1 = kvb_act(c1, n + 1);
                    c2 = kvb_act(c2, n);   c3 = kvb_act(c3, n + 1);
                }
                *(float2*)&C[(size_t)row * N + n]       = make_float2(c0, c1);
                *(float2*)&C[(size_t)(row + 8) * N + n] = make_float2(c2, c3);
            }
        }
    }
}

// ---------------------------------------------------------------------------
// In-place LayerNorm over rows of 512.  4096 blocks x 128 threads.
// ---------------------------------------------------------------------------
__global__ __launch_bounds__(128)
void ln_kernel(float* __restrict__ h, const float* __restrict__ g,
               const float* __restrict__ b)
{
    const int row = blockIdx.x;
    float* hp = h + (size_t)row * LATENT;
    const int tid = threadIdx.x;

    float4 v = ((const float4*)hp)[tid];
    float s  = v.x + v.y + v.z + v.w;
    float sq = v.x * v.x + v.y * v.y + v.z * v.z + v.w * v.w;

    __shared__ float rs[4], rq[4];
    #pragma unroll
    for (int o = 16; o; o >>= 1) {
        s  += __shfl_xor_sync(0xffffffffu, s,  o);
        sq += __shfl_xor_sync(0xffffffffu, sq, o);
    }
    if ((tid & 31) == 0) { rs[tid >> 5] = s; rq[tid >> 5] = sq; }
    __syncthreads();
    s  = rs[0] + rs[1] + rs[2] + rs[3];
    sq = rq[0] + rq[1] + rq[2] + rq[3];

    const float mu  = s * (1.f / LATENT);
    const float var = sq * (1.f / LATENT) - mu * mu;
    const float inv = rsqrtf(var + LN_EPS);

    float4 gg = ((const float4*)g)[tid];
    float4 bb = ((const float4*)b)[tid];
    v.x = (v.x - mu) * inv * gg.x + bb.x;
    v.y = (v.y - mu) * inv * gg.y + bb.y;
    v.z = (v.z - mu) * inv * gg.z + bb.z;
    v.w = (v.w - mu) * inv * gg.w + bb.w;
    ((float4*)hp)[tid] = v;
}

// ---------------------------------------------------------------------------
// Fused Oja update v3: float4 tile + streaming hints.
// One CTA per (b,h).  256 threads: c4 = tid&15 (4-col group), r4 = tid>>4
// (4-row slab).  Each thread: 4 LDG.128 (interleaved with FMAs) + 4 STG.128.
//   ks_remove[e] = sum_d W[d,e]*vs[d];  ks_ = softmax(ks-ks_remove)*lr
//   out[d,e] = vs[d]*ks_[e] + W[d,e]
// ---------------------------------------------------------------------------
__global__ __launch_bounds__(256)
void oja_kernel(const float* __restrict__ kvb, const float* __restrict__ W,
                float* __restrict__ out)
{
    const int bh = blockIdx.x;
    const int b  = bh >> 3;
    const int h  = bh & 7;

    const float*  kb  = kvb + (size_t)b * KVB_N + h * 129;
    const float4* Wp4 = (const float4*)(W   + (size_t)bh * (DHEAD * DHEAD));
    float4*       Op4 = (float4*)      (out + (size_t)bh * (DHEAD * DHEAD));

    __shared__ float ks_s[64], vs_s[64], ksf[64];
    __shared__ float red[16][64];
    __shared__ float wred[8];
    __shared__ float lr_s;

    const int tid = threadIdx.x;
    if (tid < 64)       { ks_s[tid] = kb[tid]; vs_s[tid] = kb[64 + tid]; }
    else if (tid == 64) { lr_s = kb[128]; }
    __syncthreads();

    const int c4 = tid & 15;     // column group (cols 4*c4 .. 4*c4+3)
    const int r4 = tid >> 4;     // row slab    (rows 4*r4 .. 4*r4+3)

    float4 w4[4];
    float4 ps = make_float4(0.f, 0.f, 0.f, 0.f);
    #pragma unroll
    for (int i = 0; i < 4; ++i) {
        int d = r4 * 4 + i;
        w4[i] = __ldcs(Wp4 + d * 16 + c4);       // streaming 16B read
        float v = vs_s[d];
        ps.x = fmaf(w4[i].x, v, ps.x);
        ps.y = fmaf(w4[i].y, v, ps.y);
        ps.z = fmaf(w4[i].z, v, ps.z);
        ps.w = fmaf(w4[i].w, v, ps.w);
    }
    *(float4*)&red[r4][c4 * 4] = ps;
    __syncthreads();

    // --- softmax over e (uniform control flow; tid>=64 carry neutral values)
    float v = -1e30f;
    if (tid < 64) {
        float rem = 0.f;
        #pragma unroll
        for (int s = 0; s < 16; ++s) rem += red[s][tid];
        v = ks_s[tid] - rem;
    }

    float m = v;
    #pragma unroll
    for (int o = 16; o; o >>= 1) m = fmaxf(m, __shfl_xor_sync(0xffffffffu, m, o));
    if ((tid & 31) == 0) wred[tid >> 5] = m;
    __syncthreads();
    m = wred[0];
    #pragma unroll
    for (int i = 1; i < 8; ++i) m = fmaxf(m, wred[i]);
    __syncthreads();                                  // before reusing wred

    float ex = (tid < 64) ? __expf(v - m) : 0.f;
    float sm = ex;
    #pragma unroll
    for (int o = 16; o; o >>= 1) sm += __shfl_xor_sync(0xffffffffu, sm, o);
    if ((tid & 31) == 0) wred[tid >> 5] = sm;
    __syncthreads();
    sm = wred[0] + wred[1] + wred[2] + wred[3] + wred[4] + wred[5] + wred[6] + wred[7];

    if (tid < 64) ksf[tid] = ex * lr_s / sm;
    __syncthreads();

    const float4 kf = *(const float4*)&ksf[c4 * 4];
    #pragma unroll
    for (int i = 0; i < 4; ++i) {
        int d = r4 * 4 + i;
        float v2 = vs_s[d];
        float4 o;
        o.x = fmaf(v2, kf.x, w4[i].x);
        o.y = fmaf(v2, kf.y, w4[i].y);
        o.z = fmaf(v2, kf.z, w4[i].z);
        o.w = fmaf(v2, kf.w, w4[i].w);
        __stcs(Op4 + d * 16 + c4, o);            // streaming 16B write
    }
}

// ---------------------------------------------------------------------------
// Launch (R9 grids: MT=4 / BM=128 everywhere)
// ---------------------------------------------------------------------------
extern "C" void kernel_launch(void* const* d_in, const int* in_sizes, int n_in,
                              void* d_out, int out_size)
{
    const float* x     = (const float*)d_in[0];
    const float* z     = (const float*)d_in[1];
    const float* W     = (const float*)d_in[2];
    const float* ip_w  = (const float*)d_in[3];
    const float* ip_b  = (const float*)d_in[4];
    const float* ln_g  = (const float*)d_in[5];
    const float* ln_b  = (const float*)d_in[6];
    const float* mg_w  = (const float*)d_in[7];
    const float* mg_b  = (const float*)d_in[8];
    const float* kvb_w = (const float*)d_in[9];
    const float* kvb_b = (const float*)d_in[10];
    float* out = (float*)d_out;

    void *ph, *ph2, *pkvb;
    cudaGetSymbolAddress(&ph,   g_h);
    cudaGetSymbolAddress(&ph2,  g_h2);
    cudaGetSymbolAddress(&pkvb, g_kvb);
    float* h   = (float*)ph;
    float* h2  = (float*)ph2;
    float* kvb = (float*)pkvb;

    constexpr int SM_MT4 = NSTAGE * (128 * ASTRIDE + BSZ) * 4;   // 107520 B

    cudaFuncSetAttribute(tf32_gemm<0, 4>,
                         cudaFuncAttributeMaxDynamicSharedMemorySize, SM_MT4);
    cudaFuncSetAttribute(tf32_gemm<1, 4>,
                         cudaFuncAttributeMaxDynamicSharedMemorySize, SM_MT4);

    // 1) h = x @ ip_w + ip_b               (M=4096, N=512, K=512)   128 CTAs
    tf32_gemm<0, 4><<<dim3(LATENT / BN, B_SZ / 128), 256, SM_MT4>>>(
        x, nullptr, IN_DIM, ip_w, ip_b, h, LATENT, IN_DIM);

    // 2) LayerNorm in place
    ln_kernel<<<B_SZ, 128>>>(h, ln_g, ln_b);

    // 3) h2 = concat(h, z) @ mg_w + mg_b   (K=1024, split at 512)   128 CTAs
    tf32_gemm<0, 4><<<dim3(LATENT / BN, B_SZ / 128), 256, SM_MT4>>>(
        h, z, LATENT, mg_w, mg_b, h2, LATENT, 2 * LATENT);

    // 4) kvb = act(h2 @ kvb_w + kvb_b)     (N=1032)                 288 CTAs
    tf32_gemm<1, 4><<<dim3((KVB_N + BN - 1) / BN, B_SZ / 128), 256, SM_MT4>>>(
        h2, nullptr, LATENT, kvb_w, kvb_b, kvb, KVB_N, LATENT);

    // 5) fused Oja update                  (32768 CTAs, DRAM-bound)
    oja_kernel<<<B_SZ * NHEAD, 256>>>(kvb, W, out);
}